// round 15
// baseline (speedup 1.0000x reference)
#include <cuda_runtime.h>
#include <cuda_bf16.h>
#include <cuda_fp16.h>
#include <math.h>
#include <stdint.h>

#define B_  4
#define S_  2048
#define H_  1024
#define NH_ 16
#define HD_ 64
#define M_  (B_ * S_)
#define K_  1024
#define N_  1024
#define KW_ (K_ / 2)    // 512 u32 words per row (half2-packed)

#define LOG2E 1.4426950408889634f
#define SCL   0.18033688011112042f   // 0.125 * log2(e)

// Scratch (device globals; allocation-free). All half2-packed (u32 words).
__device__ uint32_t g_xq[M_ * KW_];
__device__ uint32_t g_xk[M_ * KW_];
__device__ uint32_t g_xv[M_ * KW_];
__device__ uint32_t g_wq[N_ * KW_];
__device__ uint32_t g_wk[N_ * KW_];
__device__ uint32_t g_wv[N_ * KW_];
__device__ uint32_t g_wo[N_ * KW_];
__device__ uint32_t g_q[B_ * S_ * H_ / 2];    // fp16 [B,NH,S,HD]
__device__ uint32_t g_k[B_ * S_ * H_ / 2];    // fp16 [B,NH,S,HD]
__device__ uint32_t g_v[B_ * S_ * H_ / 2];    // fp16 [B,NH,HD,S] (transposed)
__device__ uint32_t g_ctx[B_ * S_ * H_ / 2];  // fp16 [B,S,H]
__device__ float    g_mb[B_ * S_];            // precomputed (1-m)*(-10000*log2e)

// ---------------------------------------------------------------------------
__device__ __forceinline__ uint32_t packh2(float a, float b) {
    __half2 h = __floats2half2_rn(a, b);   // low = a, high = b
    return *(uint32_t*)&h;
}
__device__ __forceinline__ float ex2(float x) {
    float y;
    asm("ex2.approx.ftz.f32 %0, %1;" : "=f"(y) : "f"(x));
    return y;
}
__device__ __forceinline__ void mma_f16(float c[4],
                                        uint32_t a0, uint32_t a1,
                                        uint32_t a2, uint32_t a3,
                                        uint32_t b0, uint32_t b1) {
    asm volatile(
        "mma.sync.aligned.m16n8k16.row.col.f32.f16.f16.f32 "
        "{%0,%1,%2,%3},{%4,%5,%6,%7},{%8,%9},{%0,%1,%2,%3};"
        : "+f"(c[0]), "+f"(c[1]), "+f"(c[2]), "+f"(c[3])
        : "r"(a0), "r"(a1), "r"(a2), "r"(a3), "r"(b0), "r"(b1));
}
__device__ __forceinline__ void ldsm4(uint32_t& r0, uint32_t& r1,
                                      uint32_t& r2, uint32_t& r3, uint32_t addr) {
    asm volatile("ldmatrix.sync.aligned.m8n8.x4.shared.b16 {%0,%1,%2,%3}, [%4];"
                 : "=r"(r0), "=r"(r1), "=r"(r2), "=r"(r3) : "r"(addr));
}
__device__ __forceinline__ void cp16(uint32_t smem, const void* g) {
    asm volatile("cp.async.cg.shared.global [%0], [%1], 16;" :: "r"(smem), "l"(g));
}
#define CP_COMMIT() asm volatile("cp.async.commit_group;")
#define CP_WAIT(N)  asm volatile("cp.async.wait_group %0;" :: "n"(N))

// ---------------------------------------------------------------------------
// Merged prepass: fp32 -> fp16 (rn), 7 jobs via blockIdx.z. 8 floats/iter.
// ---------------------------------------------------------------------------
struct CvtBatch {
    const float4* s[7];
    uint4*        d[7];
    int           n8[7];
};
__global__ void cvt7_kernel(CvtBatch cb) {
    const int z = blockIdx.z;
    const float4* __restrict__ src = cb.s[z];
    uint4* __restrict__ dst = cb.d[z];
    const int n8 = cb.n8[z];
    int i = blockIdx.x * blockDim.x + threadIdx.x;
    const int stride = gridDim.x * blockDim.x;
    for (; i < n8; i += stride) {
        float4 v0 = src[2 * i];
        float4 v1 = src[2 * i + 1];
        uint4 o;
        o.x = packh2(v0.x, v0.y);
        o.y = packh2(v0.z, v0.w);
        o.z = packh2(v1.x, v1.y);
        o.w = packh2(v1.z, v1.w);
        dst[i] = o;
    }
}

// mask prepass: madd = (1 - m) * (-10000 * log2(e))
__global__ void mask_kernel(const float* __restrict__ m, float* __restrict__ o) {
    const int i = blockIdx.x * blockDim.x + threadIdx.x;
    if (i < B_ * S_) o[i] = (1.0f - m[i]) * (-10000.0f * LOG2E);
}

// ---------------------------------------------------------------------------
// GEMM (R9 config, best measured): C = A @ W^T + bias. 128x128 tile, BK=32
// halves (16 words), 128 threads (4 warps, warp tile 64x64), 3-stage
// cp.async, one barrier per k-iter, ldmatrix fragment loads, 2 CTAs/SM.
// ---------------------------------------------------------------------------
struct GemmBatch {
    const uint32_t* A[3];
    const uint32_t* W[3];
    const float*    bias[3];
    uint32_t*       C[3];
};
#define GSTG  2560                      // 128 rows * 20 words
#define SMA0  128
#define SMB0  (128 + 3 * GSTG)
#define GEMM_SMEM ((128 + 6 * GSTG) * 4)   // 61,952 B -> 2 CTAs/SM

template <int QKV>
__global__ __launch_bounds__(128, 2)
void gemm_h(GemmBatch gb) {
    extern __shared__ uint32_t smu[];
    const uint32_t smb = (uint32_t)__cvta_generic_to_shared(smu);
    float* sbias = (float*)smu;

    const int z = QKV ? blockIdx.z : 0;
    const uint32_t* __restrict__ A = gb.A[z];
    const uint32_t* __restrict__ W = gb.W[z];
    const float*    __restrict__ bias = gb.bias[z];
    uint32_t* __restrict__ C = gb.C[z];

    const int t    = threadIdx.x;
    const int warp = t >> 5;
    const int lane = t & 31;
    const int g    = lane >> 2;
    const int tig  = lane & 3;
    const int wm   = (warp & 1) * 64;
    const int wn   = (warp >> 1) * 64;
    const int row0 = blockIdx.y * 128;
    const int col0 = blockIdx.x * 128;

    const int l8   = lane & 7;
    const int arow = l8 + ((lane >> 3) & 1) * 8;
    const int acol = ((lane >> 4) & 1) * 4;
    const int brow = l8 + ((lane >> 4) & 1) * 8;
    const int bcol = ((lane >> 3) & 1) * 4;

    const uint32_t* Ap = A + (size_t)row0 * KW_;
    const uint32_t* Wp = W + (size_t)col0 * KW_;

    sbias[t] = bias[col0 + t];

    // stage fill: 128 rows x 16 words = 512 chunks per matrix -> 4/thread
#define G_ISSUE(tt) do {                                                        \
        const int st_ = (tt) % 3;                                               \
        const int k0w_ = (tt) * 16;                                             \
        _Pragma("unroll")                                                       \
        for (int i_ = 0; i_ < 4; i_++) {                                        \
            const int idx_ = t + i_ * 128;                                      \
            const int r_ = idx_ >> 2;                                           \
            const int cw_ = (idx_ & 3) << 2;                                    \
            cp16(smb + (SMA0 + st_ * GSTG + r_ * 20 + cw_) * 4,                 \
                 Ap + (size_t)r_ * KW_ + k0w_ + cw_);                           \
            cp16(smb + (SMB0 + st_ * GSTG + r_ * 20 + cw_) * 4,                 \
                 Wp + (size_t)r_ * KW_ + k0w_ + cw_);                           \
        }                                                                       \
    } while (0)

    float acc[4][8][4];
#pragma unroll
    for (int i = 0; i < 4; i++)
#pragma unroll
        for (int j = 0; j < 8; j++)
#pragma unroll
            for (int r = 0; r < 4; r++) acc[i][j][r] = 0.f;

    G_ISSUE(0); CP_COMMIT();
    G_ISSUE(1); CP_COMMIT();

    const int NT = KW_ / 16;   // 32
    for (int tt = 0; tt < NT; tt++) {
        CP_WAIT(1);
        __syncthreads();
        if (tt + 2 < NT) G_ISSUE(tt + 2);
        CP_COMMIT();

        const uint32_t abase = smb + (SMA0 + (tt % 3) * GSTG) * 4;
        const uint32_t bbase = smb + (SMB0 + (tt % 3) * GSTG) * 4;
#pragma unroll
        for (int kkw = 0; kkw < 16; kkw += 8) {
            uint32_t af[4][4], bf[8][2];
#pragma unroll
            for (int mt = 0; mt < 4; mt++)
                ldsm4(af[mt][0], af[mt][1], af[mt][2], af[mt][3],
                      abase + ((wm + mt * 16 + arow) * 20 + kkw + acol) * 4);
#pragma unroll
            for (int np = 0; np < 4; np++)
                ldsm4(bf[np * 2][0], bf[np * 2][1], bf[np * 2 + 1][0], bf[np * 2 + 1][1],
                      bbase + ((wn + np * 16 + brow) * 20 + kkw + bcol) * 4);
#pragma unroll
            for (int mt = 0; mt < 4; mt++)
#pragma unroll
                for (int nt = 0; nt < 8; nt++)
                    mma_f16(acc[mt][nt], af[mt][0], af[mt][1], af[mt][2], af[mt][3],
                            bf[nt][0], bf[nt][1]);
        }
    }
#undef G_ISSUE

#pragma unroll
    for (int mt = 0; mt < 4; mt++) {
#pragma unroll
        for (int half = 0; half < 2; half++) {
            const int row = row0 + wm + mt * 16 + g + half * 8;
#pragma unroll
            for (int nt = 0; nt < 8; nt++) {
                const int col = col0 + wn + nt * 8 + tig * 2;
                const float vx = acc[mt][nt][half * 2 + 0] + sbias[wn + nt * 8 + tig * 2 + 0];
                const float vy = acc[mt][nt][half * 2 + 1] + sbias[wn + nt * 8 + tig * 2 + 1];
                const int bb = row >> 11, ss = row & 2047;
                const int hh = col >> 6,  dd = col & 63;
                if (!QKV) {
                    *(float2*)&((float*)C)[(size_t)row * N_ + col] = make_float2(vx, vy);
                } else if (z < 2) {
                    C[(((size_t)(bb * NH_ + hh) * S_) + ss) * (HD_ / 2) + (dd >> 1)] =
                        packh2(vx, vy);
                } else {
                    __half* Ch = (__half*)C;
                    const size_t base = ((size_t)(bb * NH_ + hh) * HD_ + dd) * S_ + ss;
                    Ch[base]      = __float2half_rn(vx);
                    Ch[base + S_] = __float2half_rn(vy);
                }
            }
        }
    }
}

// ---------------------------------------------------------------------------
// Flash attention v4: 128 threads (4 warps), warp = 32 q-rows (2 m-tiles),
// q-tile 128, kv-tile 64, triple-buffered cp.async, K/V fragments shared
// across m-tiles, P in registers, row-sum l via ones-column MMA (no sum
// reduction), precomputed mask adds. Q/K fp16 [B,NH,S,HD]; V [B,NH,HD,S].
// smem words: QP[128][36] | Ks[3][64][36] | Vt[3][64][36] | Msk[3][64]f32
// ---------------------------------------------------------------------------
#define QP_OFF   0
#define KS_OFF   4608
#define VT_OFF   11520
#define MSK_OFF  18432
#define FSTG     2304                  // 64*36
#define ATTN_SMEM ((18432 + 192) * 4)  // 74,496 B
#define ONESH2   0x3C003C00u           // half2(1.0, 1.0)

__global__ __launch_bounds__(128, 2)
void flash_attn_h4(const uint32_t* __restrict__ Q, const uint32_t* __restrict__ Kk,
                   const uint32_t* __restrict__ V, const float* __restrict__ madds,
                   uint32_t* __restrict__ ctx) {
    extern __shared__ uint32_t smu[];
    const uint32_t smbase = (uint32_t)__cvta_generic_to_shared(smu);

    const int t    = threadIdx.x;
    const int warp = t >> 5;
    const int lane = t & 31;
    const int g    = lane >> 2;
    const int tig  = lane & 3;
    const int qm   = warp * 32;        // warp q-row base (0,32,64,96)
    const int b    = blockIdx.z;
    const int h    = blockIdx.y;
    const int q0   = blockIdx.x * 128;

    const int l8   = lane & 7;
    const int arow = l8 + ((lane >> 3) & 1) * 8;    // A octet decode
    const int acol = ((lane >> 4) & 1) * 4;
    const int brow = l8 + ((lane >> 4) & 1) * 8;    // B octet decode
    const int bcol = ((lane >> 3) & 1) * 4;

    const uint32_t* qb = Q  + ((size_t)(b * NH_ + h) * S_ + q0) * (HD_ / 2);
    const uint32_t* kb = Kk + ((size_t)(b * NH_ + h) * S_) * (HD_ / 2);
    const uint32_t* vb = V  + ((size_t)(b * NH_ + h) * HD_) * (S_ / 2);
    const float*    mb = madds + (size_t)b * S_;

    // K/V tile: 64 rows x 32 words = 512 chunks -> 4/thread (128 threads)
#define F_ISSUE(tt) do {                                                          \
        const int st_ = (tt) % 3;                                                 \
        const int kvw_ = (tt) * 32;                                               \
        _Pragma("unroll")                                                         \
        for (int i = 0; i < 4; i++) {                                             \
            const int idx_ = t + i * 128;                                         \
            const int r_ = idx_ >> 3;                                             \
            const int cw_ = (idx_ & 7) << 2;                                      \
            cp16(smbase + (KS_OFF + st_ * FSTG + r_ * 36 + cw_) * 4,              \
                 kb + (size_t)((tt) * 64 + r_) * (HD_ / 2) + cw_);                \
            cp16(smbase + (VT_OFF + st_ * FSTG + r_ * 36 + cw_) * 4,              \
                 vb + (size_t)r_ * (S_ / 2) + kvw_ + cw_);                        \
        }                                                                         \
        if (t < 16)                                                               \
            cp16(smbase + (MSK_OFF + st_ * 64 + t * 4) * 4, mb + (tt) * 64 + t * 4); \
    } while (0)

    // prologue: Q tile 128 rows x 32 words = 1024 chunks -> 8/thread
#pragma unroll
    for (int i = 0; i < 8; i++) {
        const int idx_ = t + i * 128;
        const int r_ = idx_ >> 3;
        const int cw_ = (idx_ & 7) << 2;
        cp16(smbase + (QP_OFF + r_ * 36 + cw_) * 4, qb + (size_t)r_ * (HD_ / 2) + cw_);
    }
    F_ISSUE(0);
    CP_COMMIT();          // group 0: Q + tile0
    F_ISSUE(1);
    CP_COMMIT();          // group 1: tile1
    CP_WAIT(1);
    __syncthreads();

    // Q fragments: 2 m-tiles x 4 k16-chunks x 4 regs
    uint32_t qf[2][4][4];
#pragma unroll
    for (int mt = 0; mt < 2; mt++)
#pragma unroll
        for (int kc = 0; kc < 4; kc++)
            ldsm4(qf[mt][kc][0], qf[mt][kc][1], qf[mt][kc][2], qf[mt][kc][3],
                  smbase + (QP_OFF + (qm + mt * 16 + arow) * 36 + kc * 8 + acol) * 4);

    float o[2][8][4];
    float ol[2][4];                    // ones-column accumulators (row sums)
#pragma unroll
    for (int mt = 0; mt < 2; mt++) {
#pragma unroll
        for (int nt = 0; nt < 8; nt++)
#pragma unroll
            for (int r = 0; r < 4; r++) o[mt][nt][r] = 0.f;
#pragma unroll
        for (int r = 0; r < 4; r++) ol[mt][r] = 0.f;
    }
    float ms[2][2];
#pragma unroll
    for (int mt = 0; mt < 2; mt++) ms[mt][0] = ms[mt][1] = -1e30f;

    const int NT = S_ / 64;   // 32
    for (int tt = 0; tt < NT; tt++) {
        if (tt > 0) {
            CP_WAIT(1);
            __syncthreads();
        }
        if (tt + 2 < NT) F_ISSUE(tt + 2);
        CP_COMMIT();

        const int st = tt % 3;
        const uint32_t kbase = smbase + (KS_OFF + st * FSTG) * 4;
        const uint32_t vbase = smbase + (VT_OFF + st * FSTG) * 4;
        const float*   Mb = (const float*)(smu + MSK_OFF + st * 64);

        // S = Q @ K^T — K fragments loaded ONCE, shared across both m-tiles
        float s[2][8][4];
#pragma unroll
        for (int mt = 0; mt < 2; mt++)
#pragma unroll
            for (int nt = 0; nt < 8; nt++)
#pragma unroll
                for (int r = 0; r < 4; r++) s[mt][nt][r] = 0.f;
#pragma unroll
        for (int kc = 0; kc < 4; kc++) {
            uint32_t bf[8][2];
#pragma unroll
            for (int np = 0; np < 4; np++)
                ldsm4(bf[np * 2][0], bf[np * 2][1], bf[np * 2 + 1][0], bf[np * 2 + 1][1],
                      kbase + ((np * 16 + brow) * 36 + kc * 8 + bcol) * 4);
#pragma unroll
            for (int nt = 0; nt < 8; nt++) {
                mma_f16(s[0][nt], qf[0][kc][0], qf[0][kc][1], qf[0][kc][2], qf[0][kc][3],
                        bf[nt][0], bf[nt][1]);
                mma_f16(s[1][nt], qf[1][kc][0], qf[1][kc][1], qf[1][kc][2], qf[1][kc][3],
                        bf[nt][0], bf[nt][1]);
            }
        }

        // base-2 online softmax per m-tile (no sum reduction; l via ones-MMA)
#pragma unroll
        for (int mt = 0; mt < 2; mt++) {
            float rmax0 = -1e30f, rmax1 = -1e30f;
#pragma unroll
            for (int nt = 0; nt < 8; nt++) {
                const float2 mm = *(const float2*)&Mb[nt * 8 + tig * 2];
                s[mt][nt][0] = fmaf(s[mt][nt][0], SCL, mm.x);
                s[mt][nt][1] = fmaf(s[mt][nt][1], SCL, mm.y);
                s[mt][nt][2] = fmaf(s[mt][nt][2], SCL, mm.x);
                s[mt][nt][3] = fmaf(s[mt][nt][3], SCL, mm.y);
                rmax0 = fmaxf(rmax0, fmaxf(s[mt][nt][0], s[mt][nt][1]));
                rmax1 = fmaxf(rmax1, fmaxf(s[mt][nt][2], s[mt][nt][3]));
            }
#pragma unroll
            for (int off = 1; off < 4; off <<= 1) {
                rmax0 = fmaxf(rmax0, __shfl_xor_sync(0xffffffffu, rmax0, off));
                rmax1 = fmaxf(rmax1, __shfl_xor_sync(0xffffffffu, rmax1, off));
            }
            const float m0n = fmaxf(ms[mt][0], rmax0);
            const float m1n = fmaxf(ms[mt][1], rmax1);
            const float c0  = ex2(ms[mt][0] - m0n);
            const float c1  = ex2(ms[mt][1] - m1n);
            ms[mt][0] = m0n;
            ms[mt][1] = m1n;
#pragma unroll
            for (int nt = 0; nt < 8; nt++) {
                s[mt][nt][0] = ex2(s[mt][nt][0] - m0n);
                s[mt][nt][1] = ex2(s[mt][nt][1] - m0n);
                s[mt][nt][2] = ex2(s[mt][nt][2] - m1n);
                s[mt][nt][3] = ex2(s[mt][nt][3] - m1n);
                o[mt][nt][0] *= c0; o[mt][nt][1] *= c0;
                o[mt][nt][2] *= c1; o[mt][nt][3] *= c1;
            }
            ol[mt][0] *= c0; ol[mt][1] *= c0;
            ol[mt][2] *= c1; ol[mt][3] *= c1;
        }

        // O += P @ V, l += P @ 1 — P from registers, V frags shared
#pragma unroll
        for (int kc = 0; kc < 4; kc++) {
            uint32_t pa[2][4];
#pragma unroll
            for (int mt = 0; mt < 2; mt++) {
                pa[mt][0] = packh2(s[mt][2 * kc][0],     s[mt][2 * kc][1]);
                pa[mt][1] = packh2(s[mt][2 * kc][2],     s[mt][2 * kc][3]);
                pa[mt][2] = packh2(s[mt][2 * kc + 1][0], s[mt][2 * kc + 1][1]);
                pa[mt][3] = packh2(s[mt][2 * kc + 1][2], s[mt][2 * kc + 1][3]);
            }
            uint32_t bf[8][2];
#pragma unroll
            for (int np = 0; np < 4; np++)
                ldsm4(bf[np * 2][0], bf[np * 2][1], bf[np * 2 + 1][0], bf[np * 2 + 1][1],
                      vbase + ((np * 16 + brow) * 36 + kc * 8 + bcol) * 4);
#pragma unroll
            for (int nt = 0; nt < 8; nt++) {
                mma_f16(o[0][nt], pa[0][0], pa[0][1], pa[0][2], pa[0][3], bf[nt][0], bf[nt][1]);
                mma_f16(o[1][nt], pa[1][0], pa[1][1], pa[1][2], pa[1][3], bf[nt][0], bf[nt][1]);
            }
            mma_f16(ol[0], pa[0][0], pa[0][1], pa[0][2], pa[0][3], ONESH2, ONESH2);
            mma_f16(ol[1], pa[1][0], pa[1][1], pa[1][2], pa[1][3], ONESH2, ONESH2);
        }
    }
#undef F_ISSUE

    // epilogue: ctx[b][q][h*64+d] = O / l  (half2 words); l = ol cols
#pragma unroll
    for (int mt = 0; mt < 2; mt++) {
        const float inv0 = 1.0f / ol[mt][0];
        const float inv1 = 1.0f / ol[mt][2];
        const int r0 = q0 + qm + mt * 16 + g;
        const int r1 = r0 + 8;
#pragma unroll
        for (int nt = 0; nt < 8; nt++) {
            const int col = h * HD_ + nt * 8 + tig * 2;
            ctx[((size_t)b * S_ + r0) * (H_ / 2) + (col >> 1)] =
                packh2(o[mt][nt][0] * inv0, o[mt][nt][1] * inv0);
            ctx[((size_t)b * S_ + r1) * (H_ / 2) + (col >> 1)] =
                packh2(o[mt][nt][2] * inv1, o[mt][nt][3] * inv1);
        }
    }
}

// ---------------------------------------------------------------------------
extern "C" void kernel_launch(void* const* d_in, const int* in_sizes, int n_in,
                              void* d_out, int out_size) {
    const float* query = (const float*)d_in[0];
    const float* key_  = (const float*)d_in[1];
    const float* value = (const float*)d_in[2];
    const float* amask = (const float*)d_in[3];
    const float* Wq = (const float*)d_in[4];
    const float* bq = (const float*)d_in[5];
    const float* Wk = (const float*)d_in[6];
    const float* bk = (const float*)d_in[7];
    const float* Wv = (const float*)d_in[8];
    const float* bv = (const float*)d_in[9];
    const float* Wo = (const float*)d_in[10];
    const float* bo = (const float*)d_in[11];
    float* out = (float*)d_out;

    uint32_t *xq, *xk, *xv, *wq, *wk, *wv, *wo, *qp, *kp, *vp, *cp;
    float* mbp;
    cudaGetSymbolAddress((void**)&xq, g_xq);
    cudaGetSymbolAddress((void**)&xk, g_xk);
    cudaGetSymbolAddress((void**)&xv, g_xv);
    cudaGetSymbolAddress((void**)&wq, g_wq);
    cudaGetSymbolAddress((void**)&wk, g_wk);
    cudaGetSymbolAddress((void**)&wv, g_wv);
    cudaGetSymbolAddress((void**)&wo, g_wo);
    cudaGetSymbolAddress((void**)&qp, g_q);
    cudaGetSymbolAddress((void**)&kp, g_k);
    cudaGetSymbolAddress((void**)&vp, g_v);
    cudaGetSymbolAddress((void**)&cp, g_ctx);
    cudaGetSymbolAddress((void**)&mbp, g_mb);

    cudaFuncSetAttribute(gemm_h<0>, cudaFuncAttributeMaxDynamicSharedMemorySize, GEMM_SMEM);
    cudaFuncSetAttribute(gemm_h<1>, cudaFuncAttributeMaxDynamicSharedMemorySize, GEMM_SMEM);
    cudaFuncSetAttribute(flash_attn_h4, cudaFuncAttributeMaxDynamicSharedMemorySize, ATTN_SMEM);

    // merged prepass (7 jobs), fp32 -> fp16, plus mask transform
    CvtBatch cb;
    cb.s[0] = (const float4*)query; cb.d[0] = (uint4*)xq; cb.n8[0] = M_ * K_ / 8;
    cb.s[1] = (const float4*)key_;  cb.d[1] = (uint4*)xk; cb.n8[1] = M_ * K_ / 8;
    cb.s[2] = (const float4*)value; cb.d[2] = (uint4*)xv; cb.n8[2] = M_ * K_ / 8;
    cb.s[3] = (const float4*)Wq;    cb.d[3] = (uint4*)wq; cb.n8[3] = N_ * K_ / 8;
    cb.s[4] = (const float4*)Wk;    cb.d[4] = (uint4*)wk; cb.n8[4] = N_ * K_ / 8;
    cb.s[5] = (const float4*)Wv;    cb.d[5] = (uint4*)wv; cb.n8[5] = N_ * K_ / 8;
    cb.s[6] = (const float4*)Wo;    cb.d[6] = (uint4*)wo; cb.n8[6] = N_ * K_ / 8;
    cvt7_kernel<<<dim3(296, 1, 7), 256>>>(cb);
    mask_kernel<<<(B_ * S_ + 255) / 256, 256>>>(amask, mbp);

    // merged QKV projections
    GemmBatch gqkv;
    gqkv.A[0] = xq; gqkv.W[0] = wq; gqkv.bias[0] = bq; gqkv.C[0] = qp;
    gqkv.A[1] = xk; gqkv.W[1] = wk; gqkv.bias[1] = bk; gqkv.C[1] = kp;
    gqkv.A[2] = xv; gqkv.W[2] = wv; gqkv.bias[2] = bv; gqkv.C[2] = vp;
    gemm_h<1><<<dim3(N_ / 128, M_ / 128, 3), 128, GEMM_SMEM>>>(gqkv);

    flash_attn_h4<<<dim3(S_ / 128, NH_, B_), 128, ATTN_SMEM>>>(qp, kp, vp, mbp, cp);

    GemmBatch go;
    go.A[0] = cp; go.W[0] = wo; go.bias[0] = bo; go.C[0] = (uint32_t*)out;
    go.A[1] = go.A[2] = nullptr; go.W[1] = go.W[2] = nullptr;
    go.bias[1] = go.bias[2] = nullptr; go.C[1] = go.C[2] = nullptr;
    gemm_h<0><<<dim3(N_ / 128, M_ / 128, 1), 128, GEMM_SMEM>>>(go);
}

// round 16
// speedup vs baseline: 1.0135x; 1.0135x over previous
#include <cuda_runtime.h>
#include <cuda_bf16.h>
#include <cuda_fp16.h>
#include <math.h>
#include <stdint.h>

#define B_  4
#define S_  2048
#define H_  1024
#define NH_ 16
#define HD_ 64
#define M_  (B_ * S_)
#define K_  1024
#define N_  1024
#define KW_ (K_ / 2)    // 512 u32 words per row (half2-packed)

#define LOG2E 1.4426950408889634f
#define SCL   0.18033688011112042f   // 0.125 * log2(e)

// Scratch (device globals; allocation-free). All half2-packed (u32 words).
__device__ uint32_t g_xq[M_ * KW_];
__device__ uint32_t g_xk[M_ * KW_];
__device__ uint32_t g_xv[M_ * KW_];
__device__ uint32_t g_wq[N_ * KW_];
__device__ uint32_t g_wk[N_ * KW_];
__device__ uint32_t g_wv[N_ * KW_];
__device__ uint32_t g_wo[N_ * KW_];
__device__ uint32_t g_q[B_ * S_ * H_ / 2];    // fp16 [B,NH,S,HD]
__device__ uint32_t g_k[B_ * S_ * H_ / 2];    // fp16 [B,NH,S,HD]
__device__ uint32_t g_v[B_ * S_ * H_ / 2];    // fp16 [B,NH,HD,S] (transposed)
__device__ uint32_t g_ctx[B_ * S_ * H_ / 2];  // fp16 [B,S,H]
__device__ float    g_mb[B_ * S_];            // precomputed (1-m)*(-10000*log2e)

// ---------------------------------------------------------------------------
__device__ __forceinline__ uint32_t packh2(float a, float b) {
    __half2 h = __floats2half2_rn(a, b);   // low = a, high = b
    return *(uint32_t*)&h;
}
__device__ __forceinline__ float ex2(float x) {
    float y;
    asm("ex2.approx.ftz.f32 %0, %1;" : "=f"(y) : "f"(x));
    return y;
}
// pack (a,b) to half2 then 2^x elementwise — one MUFU op for two exps
__device__ __forceinline__ uint32_t exph2(float a, float b) {
    uint32_t p, r;
    asm("cvt.rn.f16x2.f32 %0, %1, %2;" : "=r"(p) : "f"(b), "f"(a));  // lo=a, hi=b
    asm("ex2.approx.f16x2 %0, %1;" : "=r"(r) : "r"(p));
    return r;
}
__device__ __forceinline__ void mma_f16(float c[4],
                                        uint32_t a0, uint32_t a1,
                                        uint32_t a2, uint32_t a3,
                                        uint32_t b0, uint32_t b1) {
    asm volatile(
        "mma.sync.aligned.m16n8k16.row.col.f32.f16.f16.f32 "
        "{%0,%1,%2,%3},{%4,%5,%6,%7},{%8,%9},{%0,%1,%2,%3};"
        : "+f"(c[0]), "+f"(c[1]), "+f"(c[2]), "+f"(c[3])
        : "r"(a0), "r"(a1), "r"(a2), "r"(a3), "r"(b0), "r"(b1));
}
__device__ __forceinline__ void ldsm4(uint32_t& r0, uint32_t& r1,
                                      uint32_t& r2, uint32_t& r3, uint32_t addr) {
    asm volatile("ldmatrix.sync.aligned.m8n8.x4.shared.b16 {%0,%1,%2,%3}, [%4];"
                 : "=r"(r0), "=r"(r1), "=r"(r2), "=r"(r3) : "r"(addr));
}
__device__ __forceinline__ void cp16(uint32_t smem, const void* g) {
    asm volatile("cp.async.cg.shared.global [%0], [%1], 16;" :: "r"(smem), "l"(g));
}
#define CP_COMMIT() asm volatile("cp.async.commit_group;")
#define CP_WAIT(N)  asm volatile("cp.async.wait_group %0;" :: "n"(N))

// ---------------------------------------------------------------------------
// Merged prepass: fp32 -> fp16 (rn), 7 jobs via blockIdx.z. 8 floats/iter.
// ---------------------------------------------------------------------------
struct CvtBatch {
    const float4* s[7];
    uint4*        d[7];
    int           n8[7];
};
__global__ void cvt7_kernel(CvtBatch cb) {
    const int z = blockIdx.z;
    const float4* __restrict__ src = cb.s[z];
    uint4* __restrict__ dst = cb.d[z];
    const int n8 = cb.n8[z];
    int i = blockIdx.x * blockDim.x + threadIdx.x;
    const int stride = gridDim.x * blockDim.x;
    for (; i < n8; i += stride) {
        float4 v0 = src[2 * i];
        float4 v1 = src[2 * i + 1];
        uint4 o;
        o.x = packh2(v0.x, v0.y);
        o.y = packh2(v0.z, v0.w);
        o.z = packh2(v1.x, v1.y);
        o.w = packh2(v1.z, v1.w);
        dst[i] = o;
    }
}

// mask prepass: madd = (1 - m) * (-10000 * log2(e))
__global__ void mask_kernel(const float* __restrict__ m, float* __restrict__ o) {
    const int i = blockIdx.x * blockDim.x + threadIdx.x;
    if (i < B_ * S_) o[i] = (1.0f - m[i]) * (-10000.0f * LOG2E);
}

// ---------------------------------------------------------------------------
// GEMM (R9 config, best measured): C = A @ W^T + bias. 128x128 tile, BK=32
// halves (16 words), 128 threads (4 warps, warp tile 64x64), 3-stage
// cp.async, one barrier per k-iter, ldmatrix fragment loads, 2 CTAs/SM.
// ---------------------------------------------------------------------------
struct GemmBatch {
    const uint32_t* A[3];
    const uint32_t* W[3];
    const float*    bias[3];
    uint32_t*       C[3];
};
#define GSTG  2560                      // 128 rows * 20 words
#define SMA0  128
#define SMB0  (128 + 3 * GSTG)
#define GEMM_SMEM ((128 + 6 * GSTG) * 4)   // 61,952 B -> 2 CTAs/SM

template <int QKV>
__global__ __launch_bounds__(128, 2)
void gemm_h(GemmBatch gb) {
    extern __shared__ uint32_t smu[];
    const uint32_t smb = (uint32_t)__cvta_generic_to_shared(smu);
    float* sbias = (float*)smu;

    const int z = QKV ? blockIdx.z : 0;
    const uint32_t* __restrict__ A = gb.A[z];
    const uint32_t* __restrict__ W = gb.W[z];
    const float*    __restrict__ bias = gb.bias[z];
    uint32_t* __restrict__ C = gb.C[z];

    const int t    = threadIdx.x;
    const int warp = t >> 5;
    const int lane = t & 31;
    const int g    = lane >> 2;
    const int tig  = lane & 3;
    const int wm   = (warp & 1) * 64;
    const int wn   = (warp >> 1) * 64;
    const int row0 = blockIdx.y * 128;
    const int col0 = blockIdx.x * 128;

    const int l8   = lane & 7;
    const int arow = l8 + ((lane >> 3) & 1) * 8;
    const int acol = ((lane >> 4) & 1) * 4;
    const int brow = l8 + ((lane >> 4) & 1) * 8;
    const int bcol = ((lane >> 3) & 1) * 4;

    const uint32_t* Ap = A + (size_t)row0 * KW_;
    const uint32_t* Wp = W + (size_t)col0 * KW_;

    sbias[t] = bias[col0 + t];

    // stage fill: 128 rows x 16 words = 512 chunks per matrix -> 4/thread
#define G_ISSUE(tt) do {                                                        \
        const int st_ = (tt) % 3;                                               \
        const int k0w_ = (tt) * 16;                                             \
        _Pragma("unroll")                                                       \
        for (int i_ = 0; i_ < 4; i_++) {                                        \
            const int idx_ = t + i_ * 128;                                      \
            const int r_ = idx_ >> 2;                                           \
            const int cw_ = (idx_ & 3) << 2;                                    \
            cp16(smb + (SMA0 + st_ * GSTG + r_ * 20 + cw_) * 4,                 \
                 Ap + (size_t)r_ * KW_ + k0w_ + cw_);                           \
            cp16(smb + (SMB0 + st_ * GSTG + r_ * 20 + cw_) * 4,                 \
                 Wp + (size_t)r_ * KW_ + k0w_ + cw_);                           \
        }                                                                       \
    } while (0)

    float acc[4][8][4];
#pragma unroll
    for (int i = 0; i < 4; i++)
#pragma unroll
        for (int j = 0; j < 8; j++)
#pragma unroll
            for (int r = 0; r < 4; r++) acc[i][j][r] = 0.f;

    G_ISSUE(0); CP_COMMIT();
    G_ISSUE(1); CP_COMMIT();

    const int NT = KW_ / 16;   // 32
    for (int tt = 0; tt < NT; tt++) {
        CP_WAIT(1);
        __syncthreads();
        if (tt + 2 < NT) G_ISSUE(tt + 2);
        CP_COMMIT();

        const uint32_t abase = smb + (SMA0 + (tt % 3) * GSTG) * 4;
        const uint32_t bbase = smb + (SMB0 + (tt % 3) * GSTG) * 4;
#pragma unroll
        for (int kkw = 0; kkw < 16; kkw += 8) {
            uint32_t af[4][4], bf[8][2];
#pragma unroll
            for (int mt = 0; mt < 4; mt++)
                ldsm4(af[mt][0], af[mt][1], af[mt][2], af[mt][3],
                      abase + ((wm + mt * 16 + arow) * 20 + kkw + acol) * 4);
#pragma unroll
            for (int np = 0; np < 4; np++)
                ldsm4(bf[np * 2][0], bf[np * 2][1], bf[np * 2 + 1][0], bf[np * 2 + 1][1],
                      bbase + ((wn + np * 16 + brow) * 20 + kkw + bcol) * 4);
#pragma unroll
            for (int mt = 0; mt < 4; mt++)
#pragma unroll
                for (int nt = 0; nt < 8; nt++)
                    mma_f16(acc[mt][nt], af[mt][0], af[mt][1], af[mt][2], af[mt][3],
                            bf[nt][0], bf[nt][1]);
        }
    }
#undef G_ISSUE

#pragma unroll
    for (int mt = 0; mt < 4; mt++) {
#pragma unroll
        for (int half = 0; half < 2; half++) {
            const int row = row0 + wm + mt * 16 + g + half * 8;
#pragma unroll
            for (int nt = 0; nt < 8; nt++) {
                const int col = col0 + wn + nt * 8 + tig * 2;
                const float vx = acc[mt][nt][half * 2 + 0] + sbias[wn + nt * 8 + tig * 2 + 0];
                const float vy = acc[mt][nt][half * 2 + 1] + sbias[wn + nt * 8 + tig * 2 + 1];
                const int bb = row >> 11, ss = row & 2047;
                const int hh = col >> 6,  dd = col & 63;
                if (!QKV) {
                    *(float2*)&((float*)C)[(size_t)row * N_ + col] = make_float2(vx, vy);
                } else if (z < 2) {
                    C[(((size_t)(bb * NH_ + hh) * S_) + ss) * (HD_ / 2) + (dd >> 1)] =
                        packh2(vx, vy);
                } else {
                    __half* Ch = (__half*)C;
                    const size_t base = ((size_t)(bb * NH_ + hh) * HD_ + dd) * S_ + ss;
                    Ch[base]      = __float2half_rn(vx);
                    Ch[base + S_] = __float2half_rn(vy);
                }
            }
        }
    }
}

// ---------------------------------------------------------------------------
// Flash attention v5: 128 threads (4 warps), warp = 32 q-rows (2 m-tiles),
// q-tile 128, kv-tile 64, triple-buffered cp.async, K/V fragments shared,
// P in registers via ex2.approx.f16x2 (exp fused with fp16 packing),
// row-sum l via ones-column MMA, precomputed mask adds.
// smem words: QP[128][36] | Ks[3][64][36] | Vt[3][64][36] | Msk[3][64]f32
// ---------------------------------------------------------------------------
#define QP_OFF   0
#define KS_OFF   4608
#define VT_OFF   11520
#define MSK_OFF  18432
#define FSTG     2304                  // 64*36
#define ATTN_SMEM ((18432 + 192) * 4)  // 74,496 B
#define ONESH2   0x3C003C00u           // half2(1.0, 1.0)

__global__ __launch_bounds__(128, 2)
void flash_attn_h5(const uint32_t* __restrict__ Q, const uint32_t* __restrict__ Kk,
                   const uint32_t* __restrict__ V, const float* __restrict__ madds,
                   uint32_t* __restrict__ ctx) {
    extern __shared__ uint32_t smu[];
    const uint32_t smbase = (uint32_t)__cvta_generic_to_shared(smu);

    const int t    = threadIdx.x;
    const int warp = t >> 5;
    const int lane = t & 31;
    const int g    = lane >> 2;
    const int tig  = lane & 3;
    const int qm   = warp * 32;        // warp q-row base (0,32,64,96)
    const int b    = blockIdx.z;
    const int h    = blockIdx.y;
    const int q0   = blockIdx.x * 128;

    const int l8   = lane & 7;
    const int arow = l8 + ((lane >> 3) & 1) * 8;    // A octet decode
    const int acol = ((lane >> 4) & 1) * 4;
    const int brow = l8 + ((lane >> 4) & 1) * 8;    // B octet decode
    const int bcol = ((lane >> 3) & 1) * 4;

    const uint32_t* qb = Q  + ((size_t)(b * NH_ + h) * S_ + q0) * (HD_ / 2);
    const uint32_t* kb = Kk + ((size_t)(b * NH_ + h) * S_) * (HD_ / 2);
    const uint32_t* vb = V  + ((size_t)(b * NH_ + h) * HD_) * (S_ / 2);
    const float*    mb = madds + (size_t)b * S_;

    // K/V tile: 64 rows x 32 words = 512 chunks -> 4/thread (128 threads)
#define F_ISSUE(tt) do {                                                          \
        const int st_ = (tt) % 3;                                                 \
        const int kvw_ = (tt) * 32;                                               \
        _Pragma("unroll")                                                         \
        for (int i = 0; i < 4; i++) {                                             \
            const int idx_ = t + i * 128;                                         \
            const int r_ = idx_ >> 3;                                             \
            const int cw_ = (idx_ & 7) << 2;                                      \
            cp16(smbase + (KS_OFF + st_ * FSTG + r_ * 36 + cw_) * 4,              \
                 kb + (size_t)((tt) * 64 + r_) * (HD_ / 2) + cw_);                \
            cp16(smbase + (VT_OFF + st_ * FSTG + r_ * 36 + cw_) * 4,              \
                 vb + (size_t)r_ * (S_ / 2) + kvw_ + cw_);                        \
        }                                                                         \
        if (t < 16)                                                               \
            cp16(smbase + (MSK_OFF + st_ * 64 + t * 4) * 4, mb + (tt) * 64 + t * 4); \
    } while (0)

    // prologue: Q tile 128 rows x 32 words = 1024 chunks -> 8/thread
#pragma unroll
    for (int i = 0; i < 8; i++) {
        const int idx_ = t + i * 128;
        const int r_ = idx_ >> 3;
        const int cw_ = (idx_ & 7) << 2;
        cp16(smbase + (QP_OFF + r_ * 36 + cw_) * 4, qb + (size_t)r_ * (HD_ / 2) + cw_);
    }
    F_ISSUE(0);
    CP_COMMIT();          // group 0: Q + tile0
    F_ISSUE(1);
    CP_COMMIT();          // group 1: tile1
    CP_WAIT(1);
    __syncthreads();

    // Q fragments: 2 m-tiles x 4 k16-chunks x 4 regs
    uint32_t qf[2][4][4];
#pragma unroll
    for (int mt = 0; mt < 2; mt++)
#pragma unroll
        for (int kc = 0; kc < 4; kc++)
            ldsm4(qf[mt][kc][0], qf[mt][kc][1], qf[mt][kc][2], qf[mt][kc][3],
                  smbase + (QP_OFF + (qm + mt * 16 + arow) * 36 + kc * 8 + acol) * 4);

    float o[2][8][4];
    float ol[2][4];                    // ones-column accumulators (row sums)
#pragma unroll
    for (int mt = 0; mt < 2; mt++) {
#pragma unroll
        for (int nt = 0; nt < 8; nt++)
#pragma unroll
            for (int r = 0; r < 4; r++) o[mt][nt][r] = 0.f;
#pragma unroll
        for (int r = 0; r < 4; r++) ol[mt][r] = 0.f;
    }
    float ms[2][2];
#pragma unroll
    for (int mt = 0; mt < 2; mt++) ms[mt][0] = ms[mt][1] = -1e30f;

    const int NT = S_ / 64;   // 32
    for (int tt = 0; tt < NT; tt++) {
        if (tt > 0) {
            CP_WAIT(1);
            __syncthreads();
        }
        if (tt + 2 < NT) F_ISSUE(tt + 2);
        CP_COMMIT();

        const int st = tt % 3;
        const uint32_t kbase = smbase + (KS_OFF + st * FSTG) * 4;
        const uint32_t vbase = smbase + (VT_OFF + st * FSTG) * 4;
        const float*   Mb = (const float*)(smu + MSK_OFF + st * 64);

        // S = Q @ K^T — K fragments loaded ONCE, shared across both m-tiles
        float s[2][8][4];
#pragma unroll
        for (int mt = 0; mt < 2; mt++)
#pragma unroll
            for (int nt = 0; nt < 8; nt++)
#pragma unroll
                for (int r = 0; r < 4; r++) s[mt][nt][r] = 0.f;
#pragma unroll
        for (int kc = 0; kc < 4; kc++) {
            uint32_t bf[8][2];
#pragma unroll
            for (int np = 0; np < 4; np++)
                ldsm4(bf[np * 2][0], bf[np * 2][1], bf[np * 2 + 1][0], bf[np * 2 + 1][1],
                      kbase + ((np * 16 + brow) * 36 + kc * 8 + bcol) * 4);
#pragma unroll
            for (int nt = 0; nt < 8; nt++) {
                mma_f16(s[0][nt], qf[0][kc][0], qf[0][kc][1], qf[0][kc][2], qf[0][kc][3],
                        bf[nt][0], bf[nt][1]);
                mma_f16(s[1][nt], qf[1][kc][0], qf[1][kc][1], qf[1][kc][2], qf[1][kc][3],
                        bf[nt][0], bf[nt][1]);
            }
        }

        // scale + mask + online max per m-tile; exp deferred to PV (f16x2)
#pragma unroll
        for (int mt = 0; mt < 2; mt++) {
            float rmax0 = -1e30f, rmax1 = -1e30f;
#pragma unroll
            for (int nt = 0; nt < 8; nt++) {
                const float2 mm = *(const float2*)&Mb[nt * 8 + tig * 2];
                s[mt][nt][0] = fmaf(s[mt][nt][0], SCL, mm.x);
                s[mt][nt][1] = fmaf(s[mt][nt][1], SCL, mm.y);
                s[mt][nt][2] = fmaf(s[mt][nt][2], SCL, mm.x);
                s[mt][nt][3] = fmaf(s[mt][nt][3], SCL, mm.y);
                rmax0 = fmaxf(rmax0, fmaxf(s[mt][nt][0], s[mt][nt][1]));
                rmax1 = fmaxf(rmax1, fmaxf(s[mt][nt][2], s[mt][nt][3]));
            }
#pragma unroll
            for (int off = 1; off < 4; off <<= 1) {
                rmax0 = fmaxf(rmax0, __shfl_xor_sync(0xffffffffu, rmax0, off));
                rmax1 = fmaxf(rmax1, __shfl_xor_sync(0xffffffffu, rmax1, off));
            }
            const float m0n = fmaxf(ms[mt][0], rmax0);
            const float m1n = fmaxf(ms[mt][1], rmax1);
            const float c0  = ex2(ms[mt][0] - m0n);
            const float c1  = ex2(ms[mt][1] - m1n);
            ms[mt][0] = m0n;
            ms[mt][1] = m1n;
#pragma unroll
            for (int nt = 0; nt < 8; nt++) {
                o[mt][nt][0] *= c0; o[mt][nt][1] *= c0;
                o[mt][nt][2] *= c1; o[mt][nt][3] *= c1;
            }
            ol[mt][0] *= c0; ol[mt][1] *= c0;
            ol[mt][2] *= c1; ol[mt][3] *= c1;
        }

        // O += P @ V, l += P @ 1 — P = 2^(s-m) computed directly in fp16
        // (exp fused with the pack that PV needed anyway), V frags shared
#pragma unroll
        for (int kc = 0; kc < 4; kc++) {
            uint32_t pa[2][4];
#pragma unroll
            for (int mt = 0; mt < 2; mt++) {
                const float m0 = ms[mt][0], m1 = ms[mt][1];
                pa[mt][0] = exph2(s[mt][2 * kc][0] - m0,     s[mt][2 * kc][1] - m0);
                pa[mt][1] = exph2(s[mt][2 * kc][2] - m1,     s[mt][2 * kc][3] - m1);
                pa[mt][2] = exph2(s[mt][2 * kc + 1][0] - m0, s[mt][2 * kc + 1][1] - m0);
                pa[mt][3] = exph2(s[mt][2 * kc + 1][2] - m1, s[mt][2 * kc + 1][3] - m1);
            }
            uint32_t bf[8][2];
#pragma unroll
            for (int np = 0; np < 4; np++)
                ldsm4(bf[np * 2][0], bf[np * 2][1], bf[np * 2 + 1][0], bf[np * 2 + 1][1],
                      vbase + ((np * 16 + brow) * 36 + kc * 8 + bcol) * 4);
#pragma unroll
            for (int nt = 0; nt < 8; nt++) {
                mma_f16(o[0][nt], pa[0][0], pa[0][1], pa[0][2], pa[0][3], bf[nt][0], bf[nt][1]);
                mma_f16(o[1][nt], pa[1][0], pa[1][1], pa[1][2], pa[1][3], bf[nt][0], bf[nt][1]);
            }
            mma_f16(ol[0], pa[0][0], pa[0][1], pa[0][2], pa[0][3], ONESH2, ONESH2);
            mma_f16(ol[1], pa[1][0], pa[1][1], pa[1][2], pa[1][3], ONESH2, ONESH2);
        }
    }
#undef F_ISSUE

    // epilogue: ctx[b][q][h*64+d] = O / l  (half2 words); l = ol cols
#pragma unroll
    for (int mt = 0; mt < 2; mt++) {
        const float inv0 = 1.0f / ol[mt][0];
        const float inv1 = 1.0f / ol[mt][2];
        const int r0 = q0 + qm + mt * 16 + g;
        const int r1 = r0 + 8;
#pragma unroll
        for (int nt = 0; nt < 8; nt++) {
            const int col = h * HD_ + nt * 8 + tig * 2;
            ctx[((size_t)b * S_ + r0) * (H_ / 2) + (col >> 1)] =
                packh2(o[mt][nt][0] * inv0, o[mt][nt][1] * inv0);
            ctx[((size_t)b * S_ + r1) * (H_ / 2) + (col >> 1)] =
                packh2(o[mt][nt][2] * inv1, o[mt][nt][3] * inv1);
        }
    }
}

// ---------------------------------------------------------------------------
extern "C" void kernel_launch(void* const* d_in, const int* in_sizes, int n_in,
                              void* d_out, int out_size) {
    const float* query = (const float*)d_in[0];
    const float* key_  = (const float*)d_in[1];
    const float* value = (const float*)d_in[2];
    const float* amask = (const float*)d_in[3];
    const float* Wq = (const float*)d_in[4];
    const float* bq = (const float*)d_in[5];
    const float* Wk = (const float*)d_in[6];
    const float* bk = (const float*)d_in[7];
    const float* Wv = (const float*)d_in[8];
    const float* bv = (const float*)d_in[9];
    const float* Wo = (const float*)d_in[10];
    const float* bo = (const float*)d_in[11];
    float* out = (float*)d_out;

    uint32_t *xq, *xk, *xv, *wq, *wk, *wv, *wo, *qp, *kp, *vp, *cp;
    float* mbp;
    cudaGetSymbolAddress((void**)&xq, g_xq);
    cudaGetSymbolAddress((void**)&xk, g_xk);
    cudaGetSymbolAddress((void**)&xv, g_xv);
    cudaGetSymbolAddress((void**)&wq, g_wq);
    cudaGetSymbolAddress((void**)&wk, g_wk);
    cudaGetSymbolAddress((void**)&wv, g_wv);
    cudaGetSymbolAddress((void**)&wo, g_wo);
    cudaGetSymbolAddress((void**)&qp, g_q);
    cudaGetSymbolAddress((void**)&kp, g_k);
    cudaGetSymbolAddress((void**)&vp, g_v);
    cudaGetSymbolAddress((void**)&cp, g_ctx);
    cudaGetSymbolAddress((void**)&mbp, g_mb);

    cudaFuncSetAttribute(gemm_h<0>, cudaFuncAttributeMaxDynamicSharedMemorySize, GEMM_SMEM);
    cudaFuncSetAttribute(gemm_h<1>, cudaFuncAttributeMaxDynamicSharedMemorySize, GEMM_SMEM);
    cudaFuncSetAttribute(flash_attn_h5, cudaFuncAttributeMaxDynamicSharedMemorySize, ATTN_SMEM);

    // merged prepass (7 jobs), fp32 -> fp16, plus mask transform
    CvtBatch cb;
    cb.s[0] = (const float4*)query; cb.d[0] = (uint4*)xq; cb.n8[0] = M_ * K_ / 8;
    cb.s[1] = (const float4*)key_;  cb.d[1] = (uint4*)xk; cb.n8[1] = M_ * K_ / 8;
    cb.s[2] = (const float4*)value; cb.d[2] = (uint4*)xv; cb.n8[2] = M_ * K_ / 8;
    cb.s[3] = (const float4*)Wq;    cb.d[3] = (uint4*)wq; cb.n8[3] = N_ * K_ / 8;
    cb.s[4] = (const float4*)Wk;    cb.d[4] = (uint4*)wk; cb.n8[4] = N_ * K_ / 8;
    cb.s[5] = (const float4*)Wv;    cb.d[5] = (uint4*)wv; cb.n8[5] = N_ * K_ / 8;
    cb.s[6] = (const float4*)Wo;    cb.d[6] = (uint4*)wo; cb.n8[6] = N_ * K_ / 8;
    cvt7_kernel<<<dim3(296, 1, 7), 256>>>(cb);
    mask_kernel<<<(B_ * S_ + 255) / 256, 256>>>(amask, mbp);

    // merged QKV projections
    GemmBatch gqkv;
    gqkv.A[0] = xq; gqkv.W[0] = wq; gqkv.bias[0] = bq; gqkv.C[0] = qp;
    gqkv.A[1] = xk; gqkv.W[1] = wk; gqkv.bias[1] = bk; gqkv.C[1] = kp;
    gqkv.A[2] = xv; gqkv.W[2] = wv; gqkv.bias[2] = bv; gqkv.C[2] = vp;
    gemm_h<1><<<dim3(N_ / 128, M_ / 128, 3), 128, GEMM_SMEM>>>(gqkv);

    flash_attn_h5<<<dim3(S_ / 128, NH_, B_), 128, ATTN_SMEM>>>(qp, kp, vp, mbp, cp);

    GemmBatch go;
    go.A[0] = cp; go.W[0] = wo; go.bias[0] = bo; go.C[0] = (uint32_t*)out;
    go.A[1] = go.A[2] = nullptr; go.W[1] = go.W[2] = nullptr;
    go.bias[1] = go.bias[2] = nullptr; go.C[1] = go.C[2] = nullptr;
    gemm_h<0><<<dim3(N_ / 128, M_ / 128, 1), 128, GEMM_SMEM>>>(go);
}